// round 8
// baseline (speedup 1.0000x reference)
#include <cuda_runtime.h>

// Problem dimensions
static constexpr int NB = 512;   // batch
static constexpr int NT = 512;   // time
static constexpr int NOBS = 64;  // obs dim
static constexpr int NH = 256;   // hidden
static constexpr int NG = 1024;  // 4*H
static constexpr int NLAT = 16;  // latent
static constexpr int NBLK = 128; // persistent grid (8 batch-tiles x 16 col-tiles)

// ---------------- scratch (device globals; no allocation allowed) ----------
__device__ float g_xp[(size_t)NT * NB * NH];   // [t*NB+b][h] = leaky(x@Wip+bip)
__device__ float g_gx[(size_t)NT * NB * NG];   // [t*NB+b][4j+g] = xp@Wi_e + b_e
__device__ float g_Wr_ie[NH * NG];             // Wi_e reordered: [k][4j+g]
__device__ float g_Wr_he[NH * NG];             // Wh_e reordered
__device__ float g_Wr_d[NH * NG];              // (Wi_d + Wh_d) reordered
__device__ float g_br_d[NG];                   // b_d reordered
__device__ float g_h[2][NB * NH];              // ping-pong hidden state
__device__ int   g_len[NB];                    // per-row valid length (prefix mask)
__device__ unsigned g_bcnt[8 * 32];            // per-group barrier counters (128B stride)
__device__ unsigned g_bep[8 * 32];             // per-group barrier epochs

// ---------------- helpers ---------------------------------------------------
union F2U { unsigned long long u; float f[2]; };

__device__ __forceinline__ void fma2(unsigned long long& d, unsigned long long a,
                                     unsigned long long b) {
    asm("fma.rn.f32x2 %0, %1, %2, %0;" : "+l"(d) : "l"(a), "l"(b));
}

// duplicate a scalar float into both lanes of a packed f32x2 register pair
__device__ __forceinline__ unsigned long long dupr(float x) {
    unsigned long long r;
    asm("mov.b64 %0, {%1, %1};" : "=l"(r) : "f"(x));
    return r;
}

__device__ __forceinline__ float fsig(float x) {
    return __fdividef(1.0f, 1.0f + __expf(-x));
}
__device__ __forceinline__ float ftanh(float x) {
    return 1.0f - __fdividef(2.0f, __expf(2.0f * x) + 1.0f);
}

// Group-local barrier: syncs the 16 blocks that share one batch tile (gid).
// Deterministic epoch targets (compile-time schedule); counters reset by k_setup.
__device__ __forceinline__ void group_barrier(int gid, unsigned target) {
    __syncthreads();
    if (threadIdx.x == 0) {
        __threadfence();
        unsigned old = atomicAdd(&g_bcnt[gid * 32], 1u);
        if (old == 15u) {
            g_bcnt[gid * 32] = 0u;
            asm volatile("st.release.gpu.global.b32 [%0], %1;"
                         :: "l"(&g_bep[gid * 32]), "r"(target) : "memory");
        } else {
            unsigned cur;
            do {
                asm volatile("ld.acquire.gpu.global.b32 %0, [%1];"
                             : "=r"(cur) : "l"(&g_bep[gid * 32]) : "memory");
            } while ((int)(cur - target) < 0);
        }
    }
    __syncthreads();
}

// ---------------- setup: weight reorder + mask lengths + barrier reset -------
__global__ void k_setup(const void* __restrict__ mask,
                        const float* __restrict__ Wi_e, const float* __restrict__ Wh_e,
                        const float* __restrict__ Wi_d, const float* __restrict__ Wh_d,
                        const float* __restrict__ b_d) {
    const int idx = blockIdx.x * 256 + threadIdx.x;   // grid 1024 x 256 = NH*NG
    {
        int k = idx >> 10, c = idx & 1023;
        int g = c & 3, j = c >> 2;
        int src = k * NG + g * NH + j;
        g_Wr_ie[idx] = Wi_e[src];
        g_Wr_he[idx] = Wh_e[src];
        g_Wr_d[idx]  = Wi_d[src] + Wh_d[src];   // decoder input == hidden -> fold
    }
    if (idx < NG) {
        int g = idx & 3, j = idx >> 2;
        g_br_d[idx] = b_d[g * NH + j];
    }
    if (idx < 8 * 32) { g_bcnt[idx] = 0u; g_bep[idx] = 0u; }
    // lengths: blocks [0, NB) each count one mask row
    if (blockIdx.x < NB) {
        const int b = blockIdx.x, tid = threadIdx.x;
        // mask[0][0] is guaranteed true; int32 read of a u8-bool row front is 0x01010101
        const bool u8 = (((const int*)mask)[0] != 1);
        int cnt = 0;
        for (int t = tid; t < NT; t += 256)
            cnt += u8 ? (((const unsigned char*)mask)[(size_t)b * NT + t] != 0)
                      : (((const int*)mask)[(size_t)b * NT + t] != 0);
#pragma unroll
        for (int off = 16; off; off >>= 1) cnt += __shfl_xor_sync(0xffffffffu, cnt, off);
        __shared__ int sred[8];
        if ((tid & 31) == 0) sred[tid >> 5] = cnt;
        __syncthreads();
        if (tid == 0) {
            int s = 0;
#pragma unroll
            for (int i = 0; i < 8; i++) s += sred[i];
            g_len[b] = s;
        }
    }
}

// ---------------- K1: input projection  xp = leaky(x @ Wip + bip) -----------
__global__ void __launch_bounds__(256) k_inproj(const float* __restrict__ x,
                                                const float* __restrict__ Wip,
                                                const float* __restrict__ bip) {
    __shared__ __align__(16) float sA[16][64];
    __shared__ __align__(16) float sB[16][64];
    const int tid = threadIdx.x;
    const int r0 = blockIdx.x * 64, c0 = blockIdx.y * 64;
    const int tx = tid & 15, ty = tid >> 4;
    const int am = tid >> 2, ak = (tid & 3) * 4;
    const int bk = tid >> 4, bc = (tid & 15) * 4;
    float acc[4][4] = {};
    for (int k0 = 0; k0 < NOBS; k0 += 16) {
        int r = r0 + am;
        int t = r >> 9;           // r / NB
        int b = r & (NB - 1);
        float4 av = *reinterpret_cast<const float4*>(&x[((size_t)b * NT + t) * NOBS + k0 + ak]);
        sA[ak + 0][am] = av.x; sA[ak + 1][am] = av.y;
        sA[ak + 2][am] = av.z; sA[ak + 3][am] = av.w;
        float4 bv = *reinterpret_cast<const float4*>(&Wip[(size_t)(k0 + bk) * NH + c0 + bc]);
        *reinterpret_cast<float4*>(&sB[bk][bc]) = bv;
        __syncthreads();
#pragma unroll
        for (int kk = 0; kk < 16; kk++) {
            float4 a4 = *reinterpret_cast<const float4*>(&sA[kk][ty * 4]);
            float4 b4 = *reinterpret_cast<const float4*>(&sB[kk][tx * 4]);
            float ar[4] = {a4.x, a4.y, a4.z, a4.w};
            float br[4] = {b4.x, b4.y, b4.z, b4.w};
#pragma unroll
            for (int i = 0; i < 4; i++)
#pragma unroll
                for (int jj = 0; jj < 4; jj++)
                    acc[i][jj] += ar[i] * br[jj];
        }
        __syncthreads();
    }
#pragma unroll
    for (int i = 0; i < 4; i++) {
        int r = r0 + ty * 4 + i;
        float4 v;
        float z0 = acc[i][0] + bip[c0 + tx * 4 + 0];
        float z1 = acc[i][1] + bip[c0 + tx * 4 + 1];
        float z2 = acc[i][2] + bip[c0 + tx * 4 + 2];
        float z3 = acc[i][3] + bip[c0 + tx * 4 + 3];
        v.x = z0 > 0.0f ? z0 : 0.01f * z0;
        v.y = z1 > 0.0f ? z1 : 0.01f * z1;
        v.z = z2 > 0.0f ? z2 : 0.01f * z2;
        v.w = z3 > 0.0f ? z3 : 0.01f * z3;
        *reinterpret_cast<float4*>(&g_xp[(size_t)r * NH + c0 + tx * 4]) = v;
    }
}

// ---------------- K2: gates_x = xp @ Wi_e_r + b_e_r  (f32x2 micro) ----------
__global__ void __launch_bounds__(256) k_gatesx(const float* __restrict__ b_e) {
    __shared__ __align__(16) float sAd[16][128];
    __shared__ __align__(16) float sB[16][64];
    const int tid = threadIdx.x;
    const size_t r0 = (size_t)blockIdx.x * 64;
    const int c0 = blockIdx.y * 64;
    const int tx = tid & 15, ty = tid >> 4;
    const int am = tid >> 2, ak = (tid & 3) * 4;
    const int bk = tid >> 4, bc = (tid & 15) * 4;
    F2U acc[4][2];
#pragma unroll
    for (int i = 0; i < 4; i++) { acc[i][0].u = 0ull; acc[i][1].u = 0ull; }
    for (int k0 = 0; k0 < NH; k0 += 16) {
        float4 av = *reinterpret_cast<const float4*>(&g_xp[(r0 + am) * NH + k0 + ak]);
        sAd[ak + 0][2 * am] = av.x; sAd[ak + 0][2 * am + 1] = av.x;
        sAd[ak + 1][2 * am] = av.y; sAd[ak + 1][2 * am + 1] = av.y;
        sAd[ak + 2][2 * am] = av.z; sAd[ak + 2][2 * am + 1] = av.z;
        sAd[ak + 3][2 * am] = av.w; sAd[ak + 3][2 * am + 1] = av.w;
        float4 bv = *reinterpret_cast<const float4*>(&g_Wr_ie[(size_t)(k0 + bk) * NG + c0 + bc]);
        *reinterpret_cast<float4*>(&sB[bk][bc]) = bv;
        __syncthreads();
#pragma unroll
        for (int kk = 0; kk < 16; kk++) {
            ulonglong2 a01 = *reinterpret_cast<const ulonglong2*>(&sAd[kk][ty * 8]);
            ulonglong2 a23 = *reinterpret_cast<const ulonglong2*>(&sAd[kk][ty * 8 + 4]);
            ulonglong2 bb  = *reinterpret_cast<const ulonglong2*>(&sB[kk][tx * 4]);
            fma2(acc[0][0].u, a01.x, bb.x); fma2(acc[0][1].u, a01.x, bb.y);
            fma2(acc[1][0].u, a01.y, bb.x); fma2(acc[1][1].u, a01.y, bb.y);
            fma2(acc[2][0].u, a23.x, bb.x); fma2(acc[2][1].u, a23.x, bb.y);
            fma2(acc[3][0].u, a23.y, bb.x); fma2(acc[3][1].u, a23.y, bb.y);
        }
        __syncthreads();
    }
    const int j = (c0 >> 2) + tx;
    const float bi_ = b_e[j], bf_ = b_e[NH + j], bg_ = b_e[2 * NH + j], bo_ = b_e[3 * NH + j];
#pragma unroll
    for (int i = 0; i < 4; i++) {
        size_t r = r0 + ty * 4 + i;
        float4 v = make_float4(acc[i][0].f[0] + bi_, acc[i][0].f[1] + bf_,
                               acc[i][1].f[0] + bg_, acc[i][1].f[1] + bo_);
        *reinterpret_cast<float4*>(&g_gx[r * NG + c0 + tx * 4]) = v;
    }
}

// ---------------- persistent scan (encoder / decoder) -----------------------
// One launch runs all steps; the 16 blocks sharing a batch tile sync through a
// group-local barrier with compile-time epoch targets (ebase = 0 enc, 512 dec).
// 512 threads (4 warps/SMSP) to hide LDS latency in the GEMM; each thread owns
// a 2-row x 4-gate-col micro-tile. The whole 64-row x 256-k h tile is staged
// into SMEM once per step ([k][row] layout, ONE __syncthreads), then 256
// k-iterations of uninterrupted compute; scalar->f32x2 dup via mov.b64 on the
// ALU pipe. Weights resident in SMEM; cell/hidden state in registers. Decoder
// fuses recon[t-1] = h_in @ Wop + bop (warps 0-7) and runs a 513th pseudo-step
// for recon[T-1].
template <bool ENC>
__global__ void __launch_bounds__(512, 1) k_scan(unsigned ebase,
                                                 const float* __restrict__ Wop,
                                                 const float* __restrict__ bop,
                                                 float* __restrict__ out) {
    extern __shared__ float sm[];
    float* sW = sm;                 // [256 k][64 gate-cols]  (64 KB, resident)
    float* sA = sm + NH * 64;       // [256 k][64 rows]       (64 KB, restaged per step)
    float* sP = sA + NH * 64;       // [256 k][4]             Wop tile (decoder only)

    const int tid = threadIdx.x;
    const int gid = blockIdx.x & 7;
    const int b0 = gid * 64;
    const int by = blockIdx.x >> 3;
    const int c0 = by * 64;
    const int tx = tid & 15, ty = tid >> 4;      // ty in [0,32): row pair
    const int j  = (c0 >> 2) + tx;
    const int pr = tid >> 2, pc = tid & 3;       // pred mapping (tid < 256)
    const bool do_pred = !ENC && (tid < 256);
    const int sr  = tid & 63;                    // staging: row
    const int sk0 = (tid >> 6) * 32;             // staging: k-chunk base (8 chunks of 32)

    // preload weight tile (once for all steps)
    const float* __restrict__ Wg = ENC ? g_Wr_he : g_Wr_d;
    for (int q = tid; q < NH * 16; q += 512) {
        int k = q >> 4, cc = (q & 15) * 4;
        *reinterpret_cast<float4*>(&sW[k * 64 + cc]) =
            *reinterpret_cast<const float4*>(&Wg[(size_t)k * NG + c0 + cc]);
    }
    float bopv = 0.0f;
    float4 bv = make_float4(0.f, 0.f, 0.f, 0.f);
    if (!ENC) {
        for (int q = tid; q < NH * 4; q += 512)
            sP[q] = Wop[(q >> 2) * NOBS + by * 4 + (q & 3)];
        bv = *reinterpret_cast<const float4*>(&g_br_d[c0 + tx * 4]);
        bopv = bop[by * 4 + pc];
    }

    float rc[2], rh[2];
    int rlen[2];
#pragma unroll
    for (int i = 0; i < 2; i++) {
        const int b = b0 + ty * 2 + i;
        if (ENC) {
            rc[i] = 0.0f; rh[i] = 0.0f; rlen[i] = g_len[b];
            g_h[0][b * NH + j] = 0.0f;             // zero initial hidden
        } else {
            float v = g_h[0][b * NH + j];          // ctx from k_latctx
            rc[i] = v; rh[i] = v; rlen[i] = 0;
        }
    }
    __syncthreads();                               // sW/sP ready
    if (ENC) group_barrier(gid, ebase + 1);        // zero-init visible in group

    // gx prefetch for step 0
    float4 gv[2];
    if (ENC) {
#pragma unroll
        for (int i = 0; i < 2; i++)
            gv[i] = *reinterpret_cast<const float4*>(
                &g_gx[(size_t)(b0 + ty * 2 + i) * NG + c0 + tx * 4]);
    }

    const int TEND = ENC ? NT : NT + 1;
    for (int t = 0; t < TEND; t++) {
        const float* __restrict__ h_in = g_h[t & 1];
        float* __restrict__ h_out = g_h[(t & 1) ^ 1];

        // ---- stage full A tile: h_in[b0+sr][sk0..sk0+31] -> sA[k][row] ----
        {
            float4 tmp[8];
#pragma unroll
            for (int i = 0; i < 8; i++)
                tmp[i] = *reinterpret_cast<const float4*>(
                    &h_in[(size_t)(b0 + sr) * NH + sk0 + 4 * i]);
#pragma unroll
            for (int i = 0; i < 8; i++) {
                sA[(sk0 + 4 * i + 0) * 64 + sr] = tmp[i].x;
                sA[(sk0 + 4 * i + 1) * 64 + sr] = tmp[i].y;
                sA[(sk0 + 4 * i + 2) * 64 + sr] = tmp[i].z;
                sA[(sk0 + 4 * i + 3) * 64 + sr] = tmp[i].w;
            }
        }
        __syncthreads();

        F2U acc[2][2];
#pragma unroll
        for (int i = 0; i < 2; i++) { acc[i][0].u = 0ull; acc[i][1].u = 0ull; }
        float accp = 0.0f;

        // ---- uninterrupted GEMM over all 256 k ----
#pragma unroll 8
        for (int k = 0; k < NH; k++) {
            float2 a2 = *reinterpret_cast<const float2*>(&sA[k * 64 + ty * 2]);
            ulonglong2 bb = *reinterpret_cast<const ulonglong2*>(&sW[k * 64 + tx * 4]);
            unsigned long long a0 = dupr(a2.x), a1 = dupr(a2.y);
            fma2(acc[0][0].u, a0, bb.x); fma2(acc[0][1].u, a0, bb.y);
            fma2(acc[1][0].u, a1, bb.x); fma2(acc[1][1].u, a1, bb.y);
            if (do_pred) accp = fmaf(sA[k * 64 + pr], sP[k * 4 + pc], accp);
        }

        if (ENC || t < NT) {
#pragma unroll
            for (int i = 0; i < 2; i++) {
                const int b = b0 + ty * 2 + i;
                float zi = acc[i][0].f[0], zf = acc[i][0].f[1];
                float zg = acc[i][1].f[0], zo = acc[i][1].f[1];
                if (ENC) { zi += gv[i].x; zf += gv[i].y; zg += gv[i].z; zo += gv[i].w; }
                else     { zi += bv.x;    zf += bv.y;    zg += bv.z;    zo += bv.w; }
                float ig = fsig(zi), fg = fsig(zf), gg = ftanh(zg), og = fsig(zo);
                float nc = fg * rc[i] + ig * gg;
                float nh = og * ftanh(nc);
                if (ENC) {
                    bool m = (t < rlen[i]);                 // prefix mask
                    rc[i] = m ? nc : rc[i];
                    rh[i] = m ? nh : rh[i];
                } else {
                    rc[i] = nc; rh[i] = nh;
                }
                h_out[b * NH + j] = rh[i];
            }
        }
        if (do_pred && t >= 1)
            out[((size_t)(b0 + pr) * NT + (t - 1)) * NOBS + by * 4 + pc] = accp + bopv;

        // prefetch gx for step t+1 (hidden behind the barrier wait)
        if (ENC && t + 1 < NT) {
#pragma unroll
            for (int i = 0; i < 2; i++)
                gv[i] = *reinterpret_cast<const float4*>(
                    &g_gx[(size_t)(t + 1) * NB * NG + (size_t)(b0 + ty * 2 + i) * NG + c0 + tx * 4]);
        }

        if (t + 1 < TEND) group_barrier(gid, ebase + (ENC ? (unsigned)(t + 2) : (unsigned)(t + 1)));
    }
}

// ---------------- latent + context (fused) -----------------------------------
__global__ void k_latctx(const float* __restrict__ Wlp, const float* __restrict__ blp,
                         const float* __restrict__ Wle, const float* __restrict__ ble,
                         float* __restrict__ out) {
    __shared__ float slat[NLAT];
    const int b = blockIdx.x, tid = threadIdx.x;
    const int l = tid >> 4, sub = tid & 15;
    const float* h = g_h[0];                 // final encoder h (512 steps -> buf 0)
    float s = 0.0f;
    for (int k = sub; k < NH; k += 16) s += h[b * NH + k] * Wlp[k * NLAT + l];
#pragma unroll
    for (int off = 8; off; off >>= 1) s += __shfl_xor_sync(0xffffffffu, s, off);
    if (sub == 0) {
        float v = s + blp[l];
        slat[l] = v;
        out[(size_t)NB * NT * NOBS + (size_t)b * NLAT + l] = v;
    }
    __syncthreads();
    float s2 = ble[tid];
#pragma unroll
    for (int l2 = 0; l2 < NLAT; l2++) s2 += slat[l2] * Wle[l2 * NH + tid];
    g_h[0][b * NH + tid] = s2 > 0.0f ? s2 : 0.01f * s2;   // ctx -> initial (c,h)
}

// ---------------- driver -----------------------------------------------------
extern "C" void kernel_launch(void* const* d_in, const int* in_sizes, int n_in,
                              void* d_out, int out_size) {
    (void)in_sizes; (void)n_in; (void)out_size;
    const float* x    = (const float*)d_in[0];
    const void*  mask = d_in[1];
    const float* Wip  = (const float*)d_in[2];
    const float* bip  = (const float*)d_in[3];
    const float* Wi_e = (const float*)d_in[4];
    const float* Wh_e = (const float*)d_in[5];
    const float* b_e  = (const float*)d_in[6];
    const float* Wlp  = (const float*)d_in[7];
    const float* blp  = (const float*)d_in[8];
    const float* Wle  = (const float*)d_in[9];
    const float* ble  = (const float*)d_in[10];
    const float* Wi_d = (const float*)d_in[11];
    const float* Wh_d = (const float*)d_in[12];
    const float* b_d  = (const float*)d_in[13];
    const float* Wop  = (const float*)d_in[14];
    const float* bop  = (const float*)d_in[15];
    float* out = (float*)d_out;

    const size_t smem_e = (size_t)(NH * 64 + NH * 64) * sizeof(float);         // 128 KB
    const size_t smem_d = smem_e + (size_t)(NH * 4) * sizeof(float);           // 132 KB
    cudaFuncSetAttribute(k_scan<true>,  cudaFuncAttributeMaxDynamicSharedMemorySize, (int)smem_d);
    cudaFuncSetAttribute(k_scan<false>, cudaFuncAttributeMaxDynamicSharedMemorySize, (int)smem_d);

    // 6 graph nodes total
    k_setup<<<1024, 256>>>(mask, Wi_e, Wh_e, Wi_d, Wh_d, b_d);
    k_inproj<<<dim3(NB * NT / 64, NH / 64), 256>>>(x, Wip, bip);
    k_gatesx<<<dim3(NB * NT / 64, NG / 64), 256>>>(b_e);
    k_scan<true><<<NBLK, 512, smem_e>>>(0u, nullptr, nullptr, nullptr);
    k_latctx<<<NB, 256>>>(Wlp, blp, Wle, ble, out);
    k_scan<false><<<NBLK, 512, smem_d>>>(512u, Wop, bop, out);
}

// round 9
// speedup vs baseline: 1.2677x; 1.2677x over previous
#include <cuda_runtime.h>

// Problem dimensions
static constexpr int NB = 512;   // batch
static constexpr int NT = 512;   // time
static constexpr int NOBS = 64;  // obs dim
static constexpr int NH = 256;   // hidden
static constexpr int NG = 1024;  // 4*H
static constexpr int NLAT = 16;  // latent
static constexpr int NBLK = 128; // persistent grid (8 batch-tiles x 16 col-tiles)

// ---------------- scratch (device globals; no allocation allowed) ----------
__device__ float g_xp[(size_t)NT * NB * NH];   // [t*NB+b][h] = leaky(x@Wip+bip)
__device__ float g_gx[(size_t)NT * NB * NG];   // [t*NB+b][4j+g] = xp@Wi_e + b_e
__device__ float g_Wr_ie[NH * NG];             // Wi_e reordered: [k][4j+g]
__device__ float g_Wr_he[NH * NG];             // Wh_e reordered
__device__ float g_Wr_d[NH * NG];              // (Wi_d + Wh_d) reordered
__device__ float g_br_d[NG];                   // b_d reordered
__device__ float g_h[2][NB * NH];              // ping-pong hidden state
__device__ int   g_len[NB];                    // per-row valid length (prefix mask)
__device__ unsigned g_bcnt[8 * 32];            // per-group barrier counters (128B stride)
__device__ unsigned g_bep[8 * 32];             // per-group barrier epochs

// ---------------- helpers ---------------------------------------------------
union F2U { unsigned long long u; float f[2]; };

__device__ __forceinline__ void fma2(unsigned long long& d, unsigned long long a,
                                     unsigned long long b) {
    asm("fma.rn.f32x2 %0, %1, %2, %0;" : "+l"(d) : "l"(a), "l"(b));
}

// duplicate a scalar float into both lanes of a packed f32x2 register pair
__device__ __forceinline__ unsigned long long dupr(float x) {
    unsigned long long r;
    asm("mov.b64 %0, {%1, %1};" : "=l"(r) : "f"(x));
    return r;
}

__device__ __forceinline__ float fsig(float x) {
    return __fdividef(1.0f, 1.0f + __expf(-x));
}
__device__ __forceinline__ float ftanh(float x) {
    return 1.0f - __fdividef(2.0f, __expf(2.0f * x) + 1.0f);
}

// Group-local barrier: syncs the 16 blocks that share one batch tile (gid).
// Deterministic epoch targets (compile-time schedule); counters reset by k_setup.
__device__ __forceinline__ void group_barrier(int gid, unsigned target) {
    __syncthreads();
    if (threadIdx.x == 0) {
        __threadfence();
        unsigned old = atomicAdd(&g_bcnt[gid * 32], 1u);
        if (old == 15u) {
            g_bcnt[gid * 32] = 0u;
            asm volatile("st.release.gpu.global.b32 [%0], %1;"
                         :: "l"(&g_bep[gid * 32]), "r"(target) : "memory");
        } else {
            unsigned cur;
            do {
                asm volatile("ld.acquire.gpu.global.b32 %0, [%1];"
                             : "=r"(cur) : "l"(&g_bep[gid * 32]) : "memory");
            } while ((int)(cur - target) < 0);
        }
    }
    __syncthreads();
}

// ---------------- setup: weight reorder + mask lengths + barrier reset -------
__global__ void k_setup(const void* __restrict__ mask,
                        const float* __restrict__ Wi_e, const float* __restrict__ Wh_e,
                        const float* __restrict__ Wi_d, const float* __restrict__ Wh_d,
                        const float* __restrict__ b_d) {
    const int idx = blockIdx.x * 256 + threadIdx.x;   // grid 1024 x 256 = NH*NG
    {
        int k = idx >> 10, c = idx & 1023;
        int g = c & 3, j = c >> 2;
        int src = k * NG + g * NH + j;
        g_Wr_ie[idx] = Wi_e[src];
        g_Wr_he[idx] = Wh_e[src];
        g_Wr_d[idx]  = Wi_d[src] + Wh_d[src];   // decoder input == hidden -> fold
    }
    if (idx < NG) {
        int g = idx & 3, j = idx >> 2;
        g_br_d[idx] = b_d[g * NH + j];
    }
    if (idx < 8 * 32) { g_bcnt[idx] = 0u; g_bep[idx] = 0u; }
    // lengths: blocks [0, NB) each count one mask row
    if (blockIdx.x < NB) {
        const int b = blockIdx.x, tid = threadIdx.x;
        // mask[0][0] is guaranteed true; int32 read of a u8-bool row front is 0x01010101
        const bool u8 = (((const int*)mask)[0] != 1);
        int cnt = 0;
        for (int t = tid; t < NT; t += 256)
            cnt += u8 ? (((const unsigned char*)mask)[(size_t)b * NT + t] != 0)
                      : (((const int*)mask)[(size_t)b * NT + t] != 0);
#pragma unroll
        for (int off = 16; off; off >>= 1) cnt += __shfl_xor_sync(0xffffffffu, cnt, off);
        __shared__ int sred[8];
        if ((tid & 31) == 0) sred[tid >> 5] = cnt;
        __syncthreads();
        if (tid == 0) {
            int s = 0;
#pragma unroll
            for (int i = 0; i < 8; i++) s += sred[i];
            g_len[b] = s;
        }
    }
}

// ---------------- K1: input projection  xp = leaky(x @ Wip + bip) -----------
__global__ void __launch_bounds__(256) k_inproj(const float* __restrict__ x,
                                                const float* __restrict__ Wip,
                                                const float* __restrict__ bip) {
    __shared__ __align__(16) float sA[16][64];
    __shared__ __align__(16) float sB[16][64];
    const int tid = threadIdx.x;
    const int r0 = blockIdx.x * 64, c0 = blockIdx.y * 64;
    const int tx = tid & 15, ty = tid >> 4;
    const int am = tid >> 2, ak = (tid & 3) * 4;
    const int bk = tid >> 4, bc = (tid & 15) * 4;
    float acc[4][4] = {};
    for (int k0 = 0; k0 < NOBS; k0 += 16) {
        int r = r0 + am;
        int t = r >> 9;           // r / NB
        int b = r & (NB - 1);
        float4 av = *reinterpret_cast<const float4*>(&x[((size_t)b * NT + t) * NOBS + k0 + ak]);
        sA[ak + 0][am] = av.x; sA[ak + 1][am] = av.y;
        sA[ak + 2][am] = av.z; sA[ak + 3][am] = av.w;
        float4 bv = *reinterpret_cast<const float4*>(&Wip[(size_t)(k0 + bk) * NH + c0 + bc]);
        *reinterpret_cast<float4*>(&sB[bk][bc]) = bv;
        __syncthreads();
#pragma unroll
        for (int kk = 0; kk < 16; kk++) {
            float4 a4 = *reinterpret_cast<const float4*>(&sA[kk][ty * 4]);
            float4 b4 = *reinterpret_cast<const float4*>(&sB[kk][tx * 4]);
            float ar[4] = {a4.x, a4.y, a4.z, a4.w};
            float br[4] = {b4.x, b4.y, b4.z, b4.w};
#pragma unroll
            for (int i = 0; i < 4; i++)
#pragma unroll
                for (int jj = 0; jj < 4; jj++)
                    acc[i][jj] += ar[i] * br[jj];
        }
        __syncthreads();
    }
#pragma unroll
    for (int i = 0; i < 4; i++) {
        int r = r0 + ty * 4 + i;
        float4 v;
        float z0 = acc[i][0] + bip[c0 + tx * 4 + 0];
        float z1 = acc[i][1] + bip[c0 + tx * 4 + 1];
        float z2 = acc[i][2] + bip[c0 + tx * 4 + 2];
        float z3 = acc[i][3] + bip[c0 + tx * 4 + 3];
        v.x = z0 > 0.0f ? z0 : 0.01f * z0;
        v.y = z1 > 0.0f ? z1 : 0.01f * z1;
        v.z = z2 > 0.0f ? z2 : 0.01f * z2;
        v.w = z3 > 0.0f ? z3 : 0.01f * z3;
        *reinterpret_cast<float4*>(&g_xp[(size_t)r * NH + c0 + tx * 4]) = v;
    }
}

// ---------------- K2: gates_x = xp @ Wi_e_r + b_e_r  (f32x2 micro) ----------
__global__ void __launch_bounds__(256) k_gatesx(const float* __restrict__ b_e) {
    __shared__ __align__(16) float sAd[16][128];
    __shared__ __align__(16) float sB[16][64];
    const int tid = threadIdx.x;
    const size_t r0 = (size_t)blockIdx.x * 64;
    const int c0 = blockIdx.y * 64;
    const int tx = tid & 15, ty = tid >> 4;
    const int am = tid >> 2, ak = (tid & 3) * 4;
    const int bk = tid >> 4, bc = (tid & 15) * 4;
    F2U acc[4][2];
#pragma unroll
    for (int i = 0; i < 4; i++) { acc[i][0].u = 0ull; acc[i][1].u = 0ull; }
    for (int k0 = 0; k0 < NH; k0 += 16) {
        float4 av = *reinterpret_cast<const float4*>(&g_xp[(r0 + am) * NH + k0 + ak]);
        sAd[ak + 0][2 * am] = av.x; sAd[ak + 0][2 * am + 1] = av.x;
        sAd[ak + 1][2 * am] = av.y; sAd[ak + 1][2 * am + 1] = av.y;
        sAd[ak + 2][2 * am] = av.z; sAd[ak + 2][2 * am + 1] = av.z;
        sAd[ak + 3][2 * am] = av.w; sAd[ak + 3][2 * am + 1] = av.w;
        float4 bv = *reinterpret_cast<const float4*>(&g_Wr_ie[(size_t)(k0 + bk) * NG + c0 + bc]);
        *reinterpret_cast<float4*>(&sB[bk][bc]) = bv;
        __syncthreads();
#pragma unroll
        for (int kk = 0; kk < 16; kk++) {
            ulonglong2 a01 = *reinterpret_cast<const ulonglong2*>(&sAd[kk][ty * 8]);
            ulonglong2 a23 = *reinterpret_cast<const ulonglong2*>(&sAd[kk][ty * 8 + 4]);
            ulonglong2 bb  = *reinterpret_cast<const ulonglong2*>(&sB[kk][tx * 4]);
            fma2(acc[0][0].u, a01.x, bb.x); fma2(acc[0][1].u, a01.x, bb.y);
            fma2(acc[1][0].u, a01.y, bb.x); fma2(acc[1][1].u, a01.y, bb.y);
            fma2(acc[2][0].u, a23.x, bb.x); fma2(acc[2][1].u, a23.x, bb.y);
            fma2(acc[3][0].u, a23.y, bb.x); fma2(acc[3][1].u, a23.y, bb.y);
        }
        __syncthreads();
    }
    const int j = (c0 >> 2) + tx;
    const float bi_ = b_e[j], bf_ = b_e[NH + j], bg_ = b_e[2 * NH + j], bo_ = b_e[3 * NH + j];
#pragma unroll
    for (int i = 0; i < 4; i++) {
        size_t r = r0 + ty * 4 + i;
        float4 v = make_float4(acc[i][0].f[0] + bi_, acc[i][0].f[1] + bf_,
                               acc[i][1].f[0] + bg_, acc[i][1].f[1] + bo_);
        *reinterpret_cast<float4*>(&g_gx[r * NG + c0 + tx * 4]) = v;
    }
}

// ---------------- persistent scan (encoder / decoder) -----------------------
// One launch runs all steps; the 16 blocks sharing a batch tile sync through a
// group-local barrier with compile-time epoch targets (ebase = 0 enc, 512 dec).
// 256 threads, 4-row x 4-gate-col micro-tiles (the LDS-traffic sweet spot:
// weight rows are read once per warp per k, 24 wf/k < 32 FMA-cyc/k). The GEMM
// inner loop is manually software-pipelined one k ahead so the 29-cyc LDS
// latency is covered by the FFMA2 stream of the previous k. Whole 64x256 h
// tile staged to SMEM once per step ([k][row], ONE __syncthreads); weights
// resident in SMEM; cell/hidden state in registers. Decoder fuses
// recon[t-1] = h_in @ Wop + bop and runs a 513th pseudo-step for recon[T-1].
template <bool ENC>
__global__ void __launch_bounds__(256, 1) k_scan(unsigned ebase,
                                                 const float* __restrict__ Wop,
                                                 const float* __restrict__ bop,
                                                 float* __restrict__ out) {
    extern __shared__ float sm[];
    float* sW = sm;                 // [256 k][64 gate-cols]  (64 KB, resident)
    float* sA = sm + NH * 64;       // [256 k][64 rows]       (64 KB, restaged per step)
    float* sP = sA + NH * 64;       // [256 k][4]             Wop tile (decoder only)

    const int tid = threadIdx.x;
    const int gid = blockIdx.x & 7;
    const int b0 = gid * 64;
    const int by = blockIdx.x >> 3;
    const int c0 = by * 64;
    const int tx = tid & 15, ty = tid >> 4;
    const int j  = (c0 >> 2) + tx;
    const int pr = tid >> 2, pc = tid & 3;
    const int sr  = tid & 63;            // staging: row
    const int sk0 = (tid >> 6) * 64;     // staging: k-chunk base (4 chunks of 64)

    // preload weight tile (once for all steps)
    const float* __restrict__ Wg = ENC ? g_Wr_he : g_Wr_d;
    for (int q = tid; q < NH * 16; q += 256) {
        int k = q >> 4, cc = (q & 15) * 4;
        *reinterpret_cast<float4*>(&sW[k * 64 + cc]) =
            *reinterpret_cast<const float4*>(&Wg[(size_t)k * NG + c0 + cc]);
    }
    float bopv = 0.0f;
    float4 bv = make_float4(0.f, 0.f, 0.f, 0.f);
    if (!ENC) {
        for (int q = tid; q < NH * 4; q += 256)
            sP[q] = Wop[(q >> 2) * NOBS + by * 4 + (q & 3)];
        bv = *reinterpret_cast<const float4*>(&g_br_d[c0 + tx * 4]);
        bopv = bop[by * 4 + pc];
    }

    float rc[4], rh[4];
    int rlen[4];
#pragma unroll
    for (int i = 0; i < 4; i++) {
        const int b = b0 + ty * 4 + i;
        if (ENC) {
            rc[i] = 0.0f; rh[i] = 0.0f; rlen[i] = g_len[b];
            g_h[0][b * NH + j] = 0.0f;             // zero initial hidden
        } else {
            float v = g_h[0][b * NH + j];          // ctx from k_latctx
            rc[i] = v; rh[i] = v; rlen[i] = 0;
        }
    }
    __syncthreads();                               // sW/sP ready
    if (ENC) group_barrier(gid, ebase + 1);        // zero-init visible in group

    // gx prefetch for step 0
    float4 gv[4];
    if (ENC) {
#pragma unroll
        for (int i = 0; i < 4; i++)
            gv[i] = *reinterpret_cast<const float4*>(
                &g_gx[(size_t)(b0 + ty * 4 + i) * NG + c0 + tx * 4]);
    }

    const int TEND = ENC ? NT : NT + 1;
    for (int t = 0; t < TEND; t++) {
        const float* __restrict__ h_in = g_h[t & 1];
        float* __restrict__ h_out = g_h[(t & 1) ^ 1];

        // ---- stage full A tile: h_in[b0+sr][sk0..sk0+63] -> sA[k][row] ----
        {
            float4 tmp[16];
#pragma unroll
            for (int i = 0; i < 16; i++)
                tmp[i] = *reinterpret_cast<const float4*>(
                    &h_in[(size_t)(b0 + sr) * NH + sk0 + 4 * i]);
#pragma unroll
            for (int i = 0; i < 16; i++) {
                sA[(sk0 + 4 * i + 0) * 64 + sr] = tmp[i].x;
                sA[(sk0 + 4 * i + 1) * 64 + sr] = tmp[i].y;
                sA[(sk0 + 4 * i + 2) * 64 + sr] = tmp[i].z;
                sA[(sk0 + 4 * i + 3) * 64 + sr] = tmp[i].w;
            }
        }
        __syncthreads();

        F2U acc[4][2];
#pragma unroll
        for (int i = 0; i < 4; i++) { acc[i][0].u = 0ull; acc[i][1].u = 0ull; }
        float accp = 0.0f;

        // ---- software-pipelined GEMM over all 256 k (1-deep prefetch) ----
        float4 a_cur = *reinterpret_cast<const float4*>(&sA[ty * 4]);
        ulonglong2 b_cur = *reinterpret_cast<const ulonglong2*>(&sW[tx * 4]);
        float p_cur = 0.0f, w_cur = 0.0f;
        if (!ENC) { p_cur = sA[pr]; w_cur = sP[pc]; }
#pragma unroll 8
        for (int k = 0; k < NH - 1; k++) {
            float4 a_nxt = *reinterpret_cast<const float4*>(&sA[(k + 1) * 64 + ty * 4]);
            ulonglong2 b_nxt = *reinterpret_cast<const ulonglong2*>(&sW[(k + 1) * 64 + tx * 4]);
            float p_nxt = 0.0f, w_nxt = 0.0f;
            if (!ENC) { p_nxt = sA[(k + 1) * 64 + pr]; w_nxt = sP[(k + 1) * 4 + pc]; }
            unsigned long long a0 = dupr(a_cur.x), a1 = dupr(a_cur.y);
            unsigned long long a2 = dupr(a_cur.z), a3 = dupr(a_cur.w);
            fma2(acc[0][0].u, a0, b_cur.x); fma2(acc[0][1].u, a0, b_cur.y);
            fma2(acc[1][0].u, a1, b_cur.x); fma2(acc[1][1].u, a1, b_cur.y);
            fma2(acc[2][0].u, a2, b_cur.x); fma2(acc[2][1].u, a2, b_cur.y);
            fma2(acc[3][0].u, a3, b_cur.x); fma2(acc[3][1].u, a3, b_cur.y);
            if (!ENC) accp = fmaf(p_cur, w_cur, accp);
            a_cur = a_nxt; b_cur = b_nxt; p_cur = p_nxt; w_cur = w_nxt;
        }
        {   // final k = NH-1 (already in registers)
            unsigned long long a0 = dupr(a_cur.x), a1 = dupr(a_cur.y);
            unsigned long long a2 = dupr(a_cur.z), a3 = dupr(a_cur.w);
            fma2(acc[0][0].u, a0, b_cur.x); fma2(acc[0][1].u, a0, b_cur.y);
            fma2(acc[1][0].u, a1, b_cur.x); fma2(acc[1][1].u, a1, b_cur.y);
            fma2(acc[2][0].u, a2, b_cur.x); fma2(acc[2][1].u, a2, b_cur.y);
            fma2(acc[3][0].u, a3, b_cur.x); fma2(acc[3][1].u, a3, b_cur.y);
            if (!ENC) accp = fmaf(p_cur, w_cur, accp);
        }

        if (ENC || t < NT) {
#pragma unroll
            for (int i = 0; i < 4; i++) {
                const int b = b0 + ty * 4 + i;
                float zi = acc[i][0].f[0], zf = acc[i][0].f[1];
                float zg = acc[i][1].f[0], zo = acc[i][1].f[1];
                if (ENC) { zi += gv[i].x; zf += gv[i].y; zg += gv[i].z; zo += gv[i].w; }
                else     { zi += bv.x;    zf += bv.y;    zg += bv.z;    zo += bv.w; }
                float ig = fsig(zi), fg = fsig(zf), gg = ftanh(zg), og = fsig(zo);
                float nc = fg * rc[i] + ig * gg;
                float nh = og * ftanh(nc);
                if (ENC) {
                    bool m = (t < rlen[i]);                 // prefix mask
                    rc[i] = m ? nc : rc[i];
                    rh[i] = m ? nh : rh[i];
                } else {
                    rc[i] = nc; rh[i] = nh;
                }
                h_out[b * NH + j] = rh[i];
            }
        }
        if (!ENC && t >= 1)
            out[((size_t)(b0 + pr) * NT + (t - 1)) * NOBS + by * 4 + pc] = accp + bopv;

        // prefetch gx for step t+1 (hidden behind the barrier wait)
        if (ENC && t + 1 < NT) {
#pragma unroll
            for (int i = 0; i < 4; i++)
                gv[i] = *reinterpret_cast<const float4*>(
                    &g_gx[(size_t)(t + 1) * NB * NG + (size_t)(b0 + ty * 4 + i) * NG + c0 + tx * 4]);
        }

        if (t + 1 < TEND) group_barrier(gid, ebase + (ENC ? (unsigned)(t + 2) : (unsigned)(t + 1)));
    }
}

// ---------------- latent + context (fused) -----------------------------------
__global__ void k_latctx(const float* __restrict__ Wlp, const float* __restrict__ blp,
                         const float* __restrict__ Wle, const float* __restrict__ ble,
                         float* __restrict__ out) {
    __shared__ float slat[NLAT];
    const int b = blockIdx.x, tid = threadIdx.x;
    const int l = tid >> 4, sub = tid & 15;
    const float* h = g_h[0];                 // final encoder h (512 steps -> buf 0)
    float s = 0.0f;
    for (int k = sub; k < NH; k += 16) s += h[b * NH + k] * Wlp[k * NLAT + l];
#pragma unroll
    for (int off = 8; off; off >>= 1) s += __shfl_xor_sync(0xffffffffu, s, off);
    if (sub == 0) {
        float v = s + blp[l];
        slat[l] = v;
        out[(size_t)NB * NT * NOBS + (size_t)b * NLAT + l] = v;
    }
    __syncthreads();
    float s2 = ble[tid];
#pragma unroll
    for (int l2 = 0; l2 < NLAT; l2++) s2 += slat[l2] * Wle[l2 * NH + tid];
    g_h[0][b * NH + tid] = s2 > 0.0f ? s2 : 0.01f * s2;   // ctx -> initial (c,h)
}

// ---------------- driver -----------------------------------------------------
extern "C" void kernel_launch(void* const* d_in, const int* in_sizes, int n_in,
                              void* d_out, int out_size) {
    (void)in_sizes; (void)n_in; (void)out_size;
    const float* x    = (const float*)d_in[0];
    const void*  mask = d_in[1];
    const float* Wip  = (const float*)d_in[2];
    const float* bip  = (const float*)d_in[3];
    const float* Wi_e = (const float*)d_in[4];
    const float* Wh_e = (const float*)d_in[5];
    const float* b_e  = (const float*)d_in[6];
    const float* Wlp  = (const float*)d_in[7];
    const float* blp  = (const float*)d_in[8];
    const float* Wle  = (const float*)d_in[9];
    const float* ble  = (const float*)d_in[10];
    const float* Wi_d = (const float*)d_in[11];
    const float* Wh_d = (const float*)d_in[12];
    const float* b_d  = (const float*)d_in[13];
    const float* Wop  = (const float*)d_in[14];
    const float* bop  = (const float*)d_in[15];
    float* out = (float*)d_out;

    const size_t smem_e = (size_t)(NH * 64 + NH * 64) * sizeof(float);         // 128 KB
    const size_t smem_d = smem_e + (size_t)(NH * 4) * sizeof(float);           // 132 KB
    cudaFuncSetAttribute(k_scan<true>,  cudaFuncAttributeMaxDynamicSharedMemorySize, (int)smem_d);
    cudaFuncSetAttribute(k_scan<false>, cudaFuncAttributeMaxDynamicSharedMemorySize, (int)smem_d);

    // 6 graph nodes total
    k_setup<<<1024, 256>>>(mask, Wi_e, Wh_e, Wi_d, Wh_d, b_d);
    k_inproj<<<dim3(NB * NT / 64, NH / 64), 256>>>(x, Wip, bip);
    k_gatesx<<<dim3(NB * NT / 64, NG / 64), 256>>>(b_e);
    k_scan<true><<<NBLK, 256, smem_e>>>(0u, nullptr, nullptr, nullptr);
    k_latctx<<<NB, 256>>>(Wlp, blp, Wle, ble, out);
    k_scan<false><<<NBLK, 256, smem_d>>>(512u, Wop, bop, out);
}

// round 10
// speedup vs baseline: 1.2718x; 1.0032x over previous
#include <cuda_runtime.h>

// Problem dimensions
static constexpr int NB = 512;   // batch
static constexpr int NT = 512;   // time
static constexpr int NOBS = 64;  // obs dim
static constexpr int NH = 256;   // hidden
static constexpr int NG = 1024;  // 4*H
static constexpr int NLAT = 16;  // latent
static constexpr int NBLK = 128; // persistent grid (8 batch-tiles x 16 col-tiles)

// ---------------- scratch (device globals; no allocation allowed) ----------
__device__ float g_xp[(size_t)NT * NB * NH];   // [t*NB+b][h] = leaky(x@Wip+bip)
__device__ float g_gx[(size_t)NT * NB * NG];   // [t*NB+b][4j+g] = xp@Wi_e + b_e
__device__ float g_Wr_ie[NH * NG];             // Wi_e reordered: [k][4j+g]
__device__ float g_Wr_he[NH * NG];             // Wh_e reordered
__device__ float g_Wr_d[NH * NG];              // (Wi_d + Wh_d) reordered
__device__ float g_br_d[NG];                   // b_d reordered
__device__ float g_h[2][NB * NH];              // ping-pong hidden state
__device__ int   g_len[NB];                    // per-row valid length (prefix mask)
__device__ unsigned g_bcnt[8 * 32];            // per-group barrier counters (128B stride)
__device__ unsigned g_bep[8 * 32];             // per-group barrier epochs

// ---------------- helpers ---------------------------------------------------
union F2U { unsigned long long u; float f[2]; };

__device__ __forceinline__ void fma2(unsigned long long& d, unsigned long long a,
                                     unsigned long long b) {
    asm("fma.rn.f32x2 %0, %1, %2, %0;" : "+l"(d) : "l"(a), "l"(b));
}

// duplicate a scalar float into both lanes of a packed f32x2 register pair
__device__ __forceinline__ unsigned long long dupr(float x) {
    unsigned long long r;
    asm("mov.b64 %0, {%1, %1};" : "=l"(r) : "f"(x));
    return r;
}

__device__ __forceinline__ float fsig(float x) {
    return __fdividef(1.0f, 1.0f + __expf(-x));
}
__device__ __forceinline__ float ftanh(float x) {
    return 1.0f - __fdividef(2.0f, __expf(2.0f * x) + 1.0f);
}

// Group-local barrier: syncs the 16 blocks that share one batch tile (gid).
// Deterministic epoch targets (compile-time schedule); counters reset by k_setup.
__device__ __forceinline__ void group_barrier(int gid, unsigned target) {
    __syncthreads();
    if (threadIdx.x == 0) {
        __threadfence();
        unsigned old = atomicAdd(&g_bcnt[gid * 32], 1u);
        if (old == 15u) {
            g_bcnt[gid * 32] = 0u;
            asm volatile("st.release.gpu.global.b32 [%0], %1;"
                         :: "l"(&g_bep[gid * 32]), "r"(target) : "memory");
        } else {
            unsigned cur;
            do {
                asm volatile("ld.acquire.gpu.global.b32 %0, [%1];"
                             : "=r"(cur) : "l"(&g_bep[gid * 32]) : "memory");
            } while ((int)(cur - target) < 0);
        }
    }
    __syncthreads();
}

// ---------------- setup: weight reorder + mask lengths + barrier reset -------
__global__ void k_setup(const void* __restrict__ mask,
                        const float* __restrict__ Wi_e, const float* __restrict__ Wh_e,
                        const float* __restrict__ Wi_d, const float* __restrict__ Wh_d,
                        const float* __restrict__ b_d) {
    const int idx = blockIdx.x * 256 + threadIdx.x;   // grid 1024 x 256 = NH*NG
    {
        int k = idx >> 10, c = idx & 1023;
        int g = c & 3, j = c >> 2;
        int src = k * NG + g * NH + j;
        g_Wr_ie[idx] = Wi_e[src];
        g_Wr_he[idx] = Wh_e[src];
        g_Wr_d[idx]  = Wi_d[src] + Wh_d[src];   // decoder input == hidden -> fold
    }
    if (idx < NG) {
        int g = idx & 3, j = idx >> 2;
        g_br_d[idx] = b_d[g * NH + j];
    }
    if (idx < 8 * 32) { g_bcnt[idx] = 0u; g_bep[idx] = 0u; }
    // lengths: blocks [0, NB) each count one mask row
    if (blockIdx.x < NB) {
        const int b = blockIdx.x, tid = threadIdx.x;
        // mask[0][0] is guaranteed true; int32 read of a u8-bool row front is 0x01010101
        const bool u8 = (((const int*)mask)[0] != 1);
        int cnt = 0;
        for (int t = tid; t < NT; t += 256)
            cnt += u8 ? (((const unsigned char*)mask)[(size_t)b * NT + t] != 0)
                      : (((const int*)mask)[(size_t)b * NT + t] != 0);
#pragma unroll
        for (int off = 16; off; off >>= 1) cnt += __shfl_xor_sync(0xffffffffu, cnt, off);
        __shared__ int sred[8];
        if ((tid & 31) == 0) sred[tid >> 5] = cnt;
        __syncthreads();
        if (tid == 0) {
            int s = 0;
#pragma unroll
            for (int i = 0; i < 8; i++) s += sred[i];
            g_len[b] = s;
        }
    }
}

// ---------------- K1: input projection  xp = leaky(x @ Wip + bip) -----------
__global__ void __launch_bounds__(256) k_inproj(const float* __restrict__ x,
                                                const float* __restrict__ Wip,
                                                const float* __restrict__ bip) {
    __shared__ __align__(16) float sA[16][64];
    __shared__ __align__(16) float sB[16][64];
    const int tid = threadIdx.x;
    const int r0 = blockIdx.x * 64, c0 = blockIdx.y * 64;
    const int tx = tid & 15, ty = tid >> 4;
    const int am = tid >> 2, ak = (tid & 3) * 4;
    const int bk = tid >> 4, bc = (tid & 15) * 4;
    float acc[4][4] = {};
    for (int k0 = 0; k0 < NOBS; k0 += 16) {
        int r = r0 + am;
        int t = r >> 9;           // r / NB
        int b = r & (NB - 1);
        float4 av = *reinterpret_cast<const float4*>(&x[((size_t)b * NT + t) * NOBS + k0 + ak]);
        sA[ak + 0][am] = av.x; sA[ak + 1][am] = av.y;
        sA[ak + 2][am] = av.z; sA[ak + 3][am] = av.w;
        float4 bv = *reinterpret_cast<const float4*>(&Wip[(size_t)(k0 + bk) * NH + c0 + bc]);
        *reinterpret_cast<float4*>(&sB[bk][bc]) = bv;
        __syncthreads();
#pragma unroll
        for (int kk = 0; kk < 16; kk++) {
            float4 a4 = *reinterpret_cast<const float4*>(&sA[kk][ty * 4]);
            float4 b4 = *reinterpret_cast<const float4*>(&sB[kk][tx * 4]);
            float ar[4] = {a4.x, a4.y, a4.z, a4.w};
            float br[4] = {b4.x, b4.y, b4.z, b4.w};
#pragma unroll
            for (int i = 0; i < 4; i++)
#pragma unroll
                for (int jj = 0; jj < 4; jj++)
                    acc[i][jj] += ar[i] * br[jj];
        }
        __syncthreads();
    }
#pragma unroll
    for (int i = 0; i < 4; i++) {
        int r = r0 + ty * 4 + i;
        float4 v;
        float z0 = acc[i][0] + bip[c0 + tx * 4 + 0];
        float z1 = acc[i][1] + bip[c0 + tx * 4 + 1];
        float z2 = acc[i][2] + bip[c0 + tx * 4 + 2];
        float z3 = acc[i][3] + bip[c0 + tx * 4 + 3];
        v.x = z0 > 0.0f ? z0 : 0.01f * z0;
        v.y = z1 > 0.0f ? z1 : 0.01f * z1;
        v.z = z2 > 0.0f ? z2 : 0.01f * z2;
        v.w = z3 > 0.0f ? z3 : 0.01f * z3;
        *reinterpret_cast<float4*>(&g_xp[(size_t)r * NH + c0 + tx * 4]) = v;
    }
}

// ---------------- K2: gates_x = xp @ Wi_e_r + b_e_r  (f32x2 micro) ----------
__global__ void __launch_bounds__(256) k_gatesx(const float* __restrict__ b_e) {
    __shared__ __align__(16) float sAd[16][128];
    __shared__ __align__(16) float sB[16][64];
    const int tid = threadIdx.x;
    const size_t r0 = (size_t)blockIdx.x * 64;
    const int c0 = blockIdx.y * 64;
    const int tx = tid & 15, ty = tid >> 4;
    const int am = tid >> 2, ak = (tid & 3) * 4;
    const int bk = tid >> 4, bc = (tid & 15) * 4;
    F2U acc[4][2];
#pragma unroll
    for (int i = 0; i < 4; i++) { acc[i][0].u = 0ull; acc[i][1].u = 0ull; }
    for (int k0 = 0; k0 < NH; k0 += 16) {
        float4 av = *reinterpret_cast<const float4*>(&g_xp[(r0 + am) * NH + k0 + ak]);
        sAd[ak + 0][2 * am] = av.x; sAd[ak + 0][2 * am + 1] = av.x;
        sAd[ak + 1][2 * am] = av.y; sAd[ak + 1][2 * am + 1] = av.y;
        sAd[ak + 2][2 * am] = av.z; sAd[ak + 2][2 * am + 1] = av.z;
        sAd[ak + 3][2 * am] = av.w; sAd[ak + 3][2 * am + 1] = av.w;
        float4 bv = *reinterpret_cast<const float4*>(&g_Wr_ie[(size_t)(k0 + bk) * NG + c0 + bc]);
        *reinterpret_cast<float4*>(&sB[bk][bc]) = bv;
        __syncthreads();
#pragma unroll
        for (int kk = 0; kk < 16; kk++) {
            ulonglong2 a01 = *reinterpret_cast<const ulonglong2*>(&sAd[kk][ty * 8]);
            ulonglong2 a23 = *reinterpret_cast<const ulonglong2*>(&sAd[kk][ty * 8 + 4]);
            ulonglong2 bb  = *reinterpret_cast<const ulonglong2*>(&sB[kk][tx * 4]);
            fma2(acc[0][0].u, a01.x, bb.x); fma2(acc[0][1].u, a01.x, bb.y);
            fma2(acc[1][0].u, a01.y, bb.x); fma2(acc[1][1].u, a01.y, bb.y);
            fma2(acc[2][0].u, a23.x, bb.x); fma2(acc[2][1].u, a23.x, bb.y);
            fma2(acc[3][0].u, a23.y, bb.x); fma2(acc[3][1].u, a23.y, bb.y);
        }
        __syncthreads();
    }
    const int j = (c0 >> 2) + tx;
    const float bi_ = b_e[j], bf_ = b_e[NH + j], bg_ = b_e[2 * NH + j], bo_ = b_e[3 * NH + j];
#pragma unroll
    for (int i = 0; i < 4; i++) {
        size_t r = r0 + ty * 4 + i;
        float4 v = make_float4(acc[i][0].f[0] + bi_, acc[i][0].f[1] + bf_,
                               acc[i][1].f[0] + bg_, acc[i][1].f[1] + bo_);
        *reinterpret_cast<float4*>(&g_gx[r * NG + c0 + tx * 4]) = v;
    }
}

// ---------------- persistent scan (encoder / decoder) -----------------------
// One launch runs all steps; the 16 blocks sharing a batch tile sync through a
// group-local barrier with compile-time epoch targets (ebase = 0 enc, 512 dec).
// SPLIT-K: 512 threads; warps 0-7 (sub-block 0) compute k in [0,128), warps
// 8-15 compute k in [128,256) for the SAME 64x64 output tile, so weight-row
// LDS traffic stays at the 8-warp level while 4 warps/SMSP hide LDS latency.
// Upper half writes partial sums to SMEM; lower half reduces, applies gates,
// and owns cell/hidden state in registers. Weights resident in SMEM; whole
// 64x256 h tile staged per step ([k][row], one __syncthreads). Decoder fuses
// recon[t-1] = h_in @ Wop + bop (also split-k) and runs a 513th pseudo-step.
template <bool ENC>
__global__ void __launch_bounds__(512, 1) k_scan(unsigned ebase,
                                                 const float* __restrict__ Wop,
                                                 const float* __restrict__ bop,
                                                 float* __restrict__ out) {
    extern __shared__ float sm[];
    float* sW  = sm;                  // [256 k][64 gate-cols]  (64 KB, resident)
    float* sA  = sm + NH * 64;        // [256 k][64 rows]       (64 KB, restaged per step)
    float* sP  = sA + NH * 64;        // [256 k][4]             Wop tile (decoder only)
    float* sR  = sP + NH * 4;         // [16][256] partial-sum reduction
    float* sRp = sR + 16 * 256;       // [256] partial pred reduction

    const int tid = threadIdx.x;
    const int sub = tid & 255;                   // position within half
    const int kb  = (tid >> 8) * 128;            // k-range base for this half
    const int gid = blockIdx.x & 7;
    const int b0 = gid * 64;
    const int by = blockIdx.x >> 3;
    const int c0 = by * 64;
    const int tx = sub & 15, ty = sub >> 4;
    const int j  = (c0 >> 2) + tx;
    const int pr = sub >> 2, pc = sub & 3;
    const int sr  = tid & 63;                    // staging: row
    const int sk0 = (tid >> 6) * 32;             // staging: k-chunk base (8 chunks of 32)

    // preload weight tile (once for all steps)
    const float* __restrict__ Wg = ENC ? g_Wr_he : g_Wr_d;
    for (int q = tid; q < NH * 16; q += 512) {
        int k = q >> 4, cc = (q & 15) * 4;
        *reinterpret_cast<float4*>(&sW[k * 64 + cc]) =
            *reinterpret_cast<const float4*>(&Wg[(size_t)k * NG + c0 + cc]);
    }
    float bopv = 0.0f;
    float4 bv = make_float4(0.f, 0.f, 0.f, 0.f);
    if (!ENC) {
        for (int q = tid; q < NH * 4; q += 512)
            sP[q] = Wop[(q >> 2) * NOBS + by * 4 + (q & 3)];
        bv = *reinterpret_cast<const float4*>(&g_br_d[c0 + tx * 4]);
        bopv = bop[by * 4 + pc];
    }

    float rc[4], rh[4];
    int rlen[4];
#pragma unroll
    for (int i = 0; i < 4; i++) {
        const int b = b0 + ty * 4 + i;
        if (ENC) {
            rc[i] = 0.0f; rh[i] = 0.0f; rlen[i] = g_len[b];
            if (tid < 256) g_h[0][b * NH + j] = 0.0f;   // zero initial hidden
        } else {
            float v = g_h[0][b * NH + j];               // ctx from k_latctx
            rc[i] = v; rh[i] = v; rlen[i] = 0;
        }
    }
    __syncthreads();                               // sW/sP ready
    if (ENC) group_barrier(gid, ebase + 1);        // zero-init visible in group

    // gx prefetch for step 0 (lower half only)
    float4 gv[4];
    if (ENC && tid < 256) {
#pragma unroll
        for (int i = 0; i < 4; i++)
            gv[i] = *reinterpret_cast<const float4*>(
                &g_gx[(size_t)(b0 + ty * 4 + i) * NG + c0 + tx * 4]);
    }

    const int TEND = ENC ? NT : NT + 1;
    for (int t = 0; t < TEND; t++) {
        const float* __restrict__ h_in = g_h[t & 1];
        float* __restrict__ h_out = g_h[(t & 1) ^ 1];

        // ---- stage full A tile: h_in[b0+sr][sk0..sk0+31] -> sA[k][row] ----
        {
            float4 tmp[8];
#pragma unroll
            for (int i = 0; i < 8; i++)
                tmp[i] = *reinterpret_cast<const float4*>(
                    &h_in[(size_t)(b0 + sr) * NH + sk0 + 4 * i]);
#pragma unroll
            for (int i = 0; i < 8; i++) {
                sA[(sk0 + 4 * i + 0) * 64 + sr] = tmp[i].x;
                sA[(sk0 + 4 * i + 1) * 64 + sr] = tmp[i].y;
                sA[(sk0 + 4 * i + 2) * 64 + sr] = tmp[i].z;
                sA[(sk0 + 4 * i + 3) * 64 + sr] = tmp[i].w;
            }
        }
        __syncthreads();

        F2U acc[4][2];
#pragma unroll
        for (int i = 0; i < 4; i++) { acc[i][0].u = 0ull; acc[i][1].u = 0ull; }
        float accp = 0.0f;

        // ---- split-k GEMM: this half covers k in [kb, kb+128) ----
        float4 a_cur = *reinterpret_cast<const float4*>(&sA[kb * 64 + ty * 4]);
        ulonglong2 b_cur = *reinterpret_cast<const ulonglong2*>(&sW[kb * 64 + tx * 4]);
        float p_cur = 0.0f, w_cur = 0.0f;
        if (!ENC) { p_cur = sA[kb * 64 + pr]; w_cur = sP[kb * 4 + pc]; }
#pragma unroll 8
        for (int k = kb; k < kb + 127; k++) {
            float4 a_nxt = *reinterpret_cast<const float4*>(&sA[(k + 1) * 64 + ty * 4]);
            ulonglong2 b_nxt = *reinterpret_cast<const ulonglong2*>(&sW[(k + 1) * 64 + tx * 4]);
            float p_nxt = 0.0f, w_nxt = 0.0f;
            if (!ENC) { p_nxt = sA[(k + 1) * 64 + pr]; w_nxt = sP[(k + 1) * 4 + pc]; }
            unsigned long long a0 = dupr(a_cur.x), a1 = dupr(a_cur.y);
            unsigned long long a2 = dupr(a_cur.z), a3 = dupr(a_cur.w);
            fma2(acc[0][0].u, a0, b_cur.x); fma2(acc[0][1].u, a0, b_cur.y);
            fma2(acc[1][0].u, a1, b_cur.x); fma2(acc[1][1].u, a1, b_cur.y);
            fma2(acc[2][0].u, a2, b_cur.x); fma2(acc[2][1].u, a2, b_cur.y);
            fma2(acc[3][0].u, a3, b_cur.x); fma2(acc[3][1].u, a3, b_cur.y);
            if (!ENC) accp = fmaf(p_cur, w_cur, accp);
            a_cur = a_nxt; b_cur = b_nxt; p_cur = p_nxt; w_cur = w_nxt;
        }
        {   // final k of this half (already in registers)
            unsigned long long a0 = dupr(a_cur.x), a1 = dupr(a_cur.y);
            unsigned long long a2 = dupr(a_cur.z), a3 = dupr(a_cur.w);
            fma2(acc[0][0].u, a0, b_cur.x); fma2(acc[0][1].u, a0, b_cur.y);
            fma2(acc[1][0].u, a1, b_cur.x); fma2(acc[1][1].u, a1, b_cur.y);
            fma2(acc[2][0].u, a2, b_cur.x); fma2(acc[2][1].u, a2, b_cur.y);
            fma2(acc[3][0].u, a3, b_cur.x); fma2(acc[3][1].u, a3, b_cur.y);
            if (!ENC) accp = fmaf(p_cur, w_cur, accp);
        }

        // ---- cross-half reduction: upper half publishes partials ----
        if (tid >= 256) {
#pragma unroll
            for (int i = 0; i < 4; i++) {
                sR[(i * 4 + 0) * 256 + sub] = acc[i][0].f[0];
                sR[(i * 4 + 1) * 256 + sub] = acc[i][0].f[1];
                sR[(i * 4 + 2) * 256 + sub] = acc[i][1].f[0];
                sR[(i * 4 + 3) * 256 + sub] = acc[i][1].f[1];
            }
            if (!ENC) sRp[sub] = accp;
        }
        __syncthreads();

        if (tid < 256 && (ENC || t < NT)) {
#pragma unroll
            for (int i = 0; i < 4; i++) {
                const int b = b0 + ty * 4 + i;
                float zi = acc[i][0].f[0] + sR[(i * 4 + 0) * 256 + sub];
                float zf = acc[i][0].f[1] + sR[(i * 4 + 1) * 256 + sub];
                float zg = acc[i][1].f[0] + sR[(i * 4 + 2) * 256 + sub];
                float zo = acc[i][1].f[1] + sR[(i * 4 + 3) * 256 + sub];
                if (ENC) { zi += gv[i].x; zf += gv[i].y; zg += gv[i].z; zo += gv[i].w; }
                else     { zi += bv.x;    zf += bv.y;    zg += bv.z;    zo += bv.w; }
                float ig = fsig(zi), fg = fsig(zf), gg = ftanh(zg), og = fsig(zo);
                float nc = fg * rc[i] + ig * gg;
                float nh = og * ftanh(nc);
                if (ENC) {
                    bool m = (t < rlen[i]);                 // prefix mask
                    rc[i] = m ? nc : rc[i];
                    rh[i] = m ? nh : rh[i];
                } else {
                    rc[i] = nc; rh[i] = nh;
                }
                h_out[b * NH + j] = rh[i];
            }
        }
        if (!ENC && tid < 256 && t >= 1)
            out[((size_t)(b0 + pr) * NT + (t - 1)) * NOBS + by * 4 + pc] =
                accp + sRp[sub] + bopv;

        // prefetch gx for step t+1 (hidden behind the barrier wait)
        if (ENC && tid < 256 && t + 1 < NT) {
#pragma unroll
            for (int i = 0; i < 4; i++)
                gv[i] = *reinterpret_cast<const float4*>(
                    &g_gx[(size_t)(t + 1) * NB * NG + (size_t)(b0 + ty * 4 + i) * NG + c0 + tx * 4]);
        }

        if (t + 1 < TEND) group_barrier(gid, ebase + (ENC ? (unsigned)(t + 2) : (unsigned)(t + 1)));
    }
}

// ---------------- latent + context (fused) -----------------------------------
__global__ void k_latctx(const float* __restrict__ Wlp, const float* __restrict__ blp,
                         const float* __restrict__ Wle, const float* __restrict__ ble,
                         float* __restrict__ out) {
    __shared__ float slat[NLAT];
    const int b = blockIdx.x, tid = threadIdx.x;
    const int l = tid >> 4, sub = tid & 15;
    const float* h = g_h[0];                 // final encoder h (512 steps -> buf 0)
    float s = 0.0f;
    for (int k = sub; k < NH; k += 16) s += h[b * NH + k] * Wlp[k * NLAT + l];
#pragma unroll
    for (int off = 8; off; off >>= 1) s += __shfl_xor_sync(0xffffffffu, s, off);
    if (sub == 0) {
        float v = s + blp[l];
        slat[l] = v;
        out[(size_t)NB * NT * NOBS + (size_t)b * NLAT + l] = v;
    }
    __syncthreads();
    float s2 = ble[tid];
#pragma unroll
    for (int l2 = 0; l2 < NLAT; l2++) s2 += slat[l2] * Wle[l2 * NH + tid];
    g_h[0][b * NH + tid] = s2 > 0.0f ? s2 : 0.01f * s2;   // ctx -> initial (c,h)
}

// ---------------- driver -----------------------------------------------------
extern "C" void kernel_launch(void* const* d_in, const int* in_sizes, int n_in,
                              void* d_out, int out_size) {
    (void)in_sizes; (void)n_in; (void)out_size;
    const float* x    = (const float*)d_in[0];
    const void*  mask = d_in[1];
    const float* Wip  = (const float*)d_in[2];
    const float* bip  = (const float*)d_in[3];
    const float* Wi_e = (const float*)d_in[4];
    const float* Wh_e = (const float*)d_in[5];
    const float* b_e  = (const float*)d_in[6];
    const float* Wlp  = (const float*)d_in[7];
    const float* blp  = (const float*)d_in[8];
    const float* Wle  = (const float*)d_in[9];
    const float* ble  = (const float*)d_in[10];
    const float* Wi_d = (const float*)d_in[11];
    const float* Wh_d = (const float*)d_in[12];
    const float* b_d  = (const float*)d_in[13];
    const float* Wop  = (const float*)d_in[14];
    const float* bop  = (const float*)d_in[15];
    float* out = (float*)d_out;

    // smem: sW 64K + sA 64K + sP 4K + sR 16K + sRp 1K = 149 KB
    const size_t smem = (size_t)(NH * 64 + NH * 64 + NH * 4 + 16 * 256 + 256) * sizeof(float);
    cudaFuncSetAttribute(k_scan<true>,  cudaFuncAttributeMaxDynamicSharedMemorySize, (int)smem);
    cudaFuncSetAttribute(k_scan<false>, cudaFuncAttributeMaxDynamicSharedMemorySize, (int)smem);

    // 6 graph nodes total
    k_setup<<<1024, 256>>>(mask, Wi_e, Wh_e, Wi_d, Wh_d, b_d);
    k_inproj<<<dim3(NB * NT / 64, NH / 64), 256>>>(x, Wip, bip);
    k_gatesx<<<dim3(NB * NT / 64, NG / 64), 256>>>(b_e);
    k_scan<true><<<NBLK, 512, smem>>>(0u, nullptr, nullptr, nullptr);
    k_latctx<<<NB, 256>>>(Wlp, blp, Wle, ble, out);
    k_scan<false><<<NBLK, 512, smem>>>(512u, Wop, bop, out);
}